// round 16
// baseline (speedup 1.0000x reference)
#include <cuda_runtime.h>
#include <cuda_fp16.h>
#include <cstdint>

#define NN   32
#define CC   256
#define HH   56
#define WW   56
#define SS   3136
#define NPOS 100352
#define CS   802816
#define TOT  25690112
#define EPSV 1e-5
#define PB   128
#define NBLK (NPOS/PB)      // 784
#define BOXB (NPOS/256)     // 392

// ---------------- scratch ----------------
__device__ __align__(16) unsigned g_xb [NPOS * 8];
__device__ __align__(16) unsigned g_xb2[NPOS * 8];
__device__ __align__(16) short    g_P  [NPOS];
__device__ __align__(16) short    g_T  [NPOS];
__device__ __align__(16) short    g_P2 [NPOS];
__device__ __align__(16) short    g_y1 [TOT];
__device__ __align__(16) short    g_y2 [TOT];
__device__ __align__(16) __half   g_u  [TOT];     // fast path: fp16 mid value u
__device__ float     g_scale1[CC], g_scale2[CC];
__device__ unsigned  g_ent3[CC * 2304];
__device__ int       g_cnt3[CC];
__device__ unsigned  g_ent1[CC * 256];
__device__ int       g_cnt1[CC];
// Monotone guard flags: statically 0; set (never cleared) by k_wprep when any
// weight <= 0. Weights are constant within a bench run, so the value is
// identical on every replay, and the first launch sets it before any consumer.
__device__ int       g_bad3 = 0, g_bad2 = 0;
__device__ long long g_partT[BOXB], g_partT2[BOXB];
__device__ long long g_partP2[NBLK], g_partP2q[NBLK];
__device__ long long g_s1[CC], g_s1q[CC], g_s2[CC], g_s2q[CC];
__device__ float     g_a1[CC], g_c1[CC], g_a2[CC], g_c2[CC];

__device__ __forceinline__ void atomAddLL(long long* p, long long v) {
    atomicAdd((unsigned long long*)p, (unsigned long long)v);
}

// ---------------- k_wprep: weight scales + sparse corrections + guard flags ----------------
__global__ __launch_bounds__(256) void k_wprep(const float* __restrict__ w3,
                                               const float* __restrict__ wr) {
    __shared__ float red[256];
    int b = blockIdx.x, t = threadIdx.x;
    if (b < CC) {
        int o = b;
        if (t == 0) { g_cnt3[o] = 0; g_s1[o] = 0; g_s1q[o] = 0; }
        __syncthreads();
        float sum = 0.f;
        for (int j = t; j < 2304; j += 256) {
            float v = w3[o * 2304 + j];
            sum += fabsf(v);
            if (v <= 0.f) {
                int slot = atomicAdd(&g_cnt3[o], 1);
                g_ent3[o * 2304 + slot] =
                    (unsigned)(((j / 9) << 5) | ((j % 9) << 1) | (v < 0.f ? 1 : 0));
            }
        }
        red[t] = sum; __syncthreads();
        for (int st = 128; st > 0; st >>= 1) { if (t < st) red[t] += red[t + st]; __syncthreads(); }
        if (t == 0) {
            g_scale1[o] = red[0] / 2304.f;
            if (g_cnt3[o] > 0) atomicExch(&g_bad3, 1);
        }
    } else {
        int o = b - CC;
        if (t == 0) { g_cnt1[o] = 0; g_s2[o] = 0; g_s2q[o] = 0; }
        __syncthreads();
        float v = wr[o * 256 + t];
        if (v <= 0.f) {
            int slot = atomicAdd(&g_cnt1[o], 1);
            g_ent1[o * 256 + slot] = (unsigned)((t << 1) | (v < 0.f ? 1 : 0));
        }
        red[t] = fabsf(v); __syncthreads();
        for (int st = 128; st > 0; st >>= 1) { if (t < st) red[t] += red[t + st]; __syncthreads(); }
        if (t == 0) {
            g_scale2[o] = red[0] / 256.f;
            if (g_cnt1[o] > 0) atomicExch(&g_bad2, 1);
        }
    }
}

// ---------------- kA: sign(x+b1_1) bits + P (bit-planes stored only if slow path needed) ----------------
__global__ __launch_bounds__(256) void kA(const float* __restrict__ x,
                                          const float* __restrict__ b1_1) {
    __shared__ float    sb[256];
    __shared__ unsigned sw[8][132];
    int bs = blockIdx.x;
    int tx = threadIdx.x, ty = threadIdx.y, t = ty * 32 + tx;
    sb[t] = b1_1[t];
    __syncthreads();
    int p0 = bs * PB + tx * 4;
    int n = p0 / SS, s = p0 % SS;
    const float* xp = x + (size_t)n * CS + s;
    unsigned w0 = 0, w1 = 0, w2 = 0, w3v = 0;
    #pragma unroll
    for (int it = 0; it < 32; it++) {
        int c = ty * 32 + it;
        float4 v = *(const float4*)(xp + (size_t)c * SS);
        float nb = -sb[c];
        w0 |= (unsigned)(v.x >= nb) << it;
        w1 |= (unsigned)(v.y >= nb) << it;
        w2 |= (unsigned)(v.z >= nb) << it;
        w3v |= (unsigned)(v.w >= nb) << it;
    }
    sw[ty][tx * 4 + 0] = w0; sw[ty][tx * 4 + 1] = w1;
    sw[ty][tx * 4 + 2] = w2; sw[ty][tx * 4 + 3] = w3v;
    __syncthreads();
    if (g_bad3 != 0) {
        #pragma unroll
        for (int i = t; i < 1024; i += 256)
            g_xb[(size_t)bs * 1024 + i] = sw[i & 7][i >> 3];
    }
    if (t < 128) {
        int P = 0;
        #pragma unroll
        for (int k = 0; k < 8; k++) P += 2 * __popc(sw[k][t]) - 32;
        g_P[bs * PB + t] = (short)P;
    }
}

// ---------------- k_boxconv: T = box3x3(P) + partial stats (+ fused exact conv1) ----------------
__global__ __launch_bounds__(256) void k_boxconv() {
    int b = blockIdx.x, t = threadIdx.x;
    if (b < BOXB) {
        __shared__ int rw1[8], rw2[8];
        int p = b * 256 + t;
        int n = p / SS, s = p % SS;
        int h = s / WW, w = s % WW;
        int T = 0;
        #pragma unroll
        for (int dh = -1; dh <= 1; dh++) {
            int hh = h + dh; if (hh < 0 || hh >= HH) continue;
            #pragma unroll
            for (int dw = -1; dw <= 1; dw++) {
                int ww = w + dw; if (ww < 0 || ww >= WW) continue;
                T += g_P[n * SS + hh * WW + ww];
            }
        }
        g_T[p] = (short)T;
        int v1 = T, v2 = T * T;
        #pragma unroll
        for (int m = 16; m > 0; m >>= 1) {
            v1 += __shfl_xor_sync(0xffffffffu, v1, m);
            v2 += __shfl_xor_sync(0xffffffffu, v2, m);
        }
        if ((t & 31) == 0) { rw1[t >> 5] = v1; rw2[t >> 5] = v2; }
        __syncthreads();
        if (t == 0) {
            long long s1 = 0, s2 = 0;
            #pragma unroll
            for (int k = 0; k < 8; k++) { s1 += rw1[k]; s2 += rw2[k]; }
            g_partT[b] = s1; g_partT2[b] = s2;
        }
    } else {
        if (g_bad3 == 0) return;
        int o = t;
        int cnt = g_cnt3[o];
        if (cnt == 0) return;
        int bb = b - BOXB;
        int n = bb / HH, h = bb % HH;
        const unsigned* ent = &g_ent3[o * 2304];
        long long accI = 0, accI2 = 0;
        for (int w = 0; w < WW; w++) {
            int T = 0;
            for (int dh = -1; dh <= 1; dh++) {
                int hh = h + dh; if (hh < 0 || hh >= HH) continue;
                for (int dw = -1; dw <= 1; dw++) {
                    int ww = w + dw; if (ww < 0 || ww >= WW) continue;
                    T += g_P[n * SS + hh * WW + ww];
                }
            }
            int I = T;
            for (int e = 0; e < cnt; e++) {
                unsigned en = ent[e];
                int neg = en & 1, tap = (en >> 1) & 15, i = en >> 5;
                int hh = h + tap / 3 - 1, ww = w + tap % 3 - 1;
                if (hh >= 0 && hh < HH && ww >= 0 && ww < WW) {
                    unsigned word = g_xb[(n * SS + hh * WW + ww) * 8 + (i >> 5)];
                    int sx = ((word >> (i & 31)) & 1) ? 1 : -1;
                    I += (neg ? -2 : -1) * sx;
                }
            }
            g_y1[(size_t)(n * CC + o) * SS + h * WW + w] = (short)I;
            accI += I; accI2 += (long long)I * I;
        }
        atomAddLL(&g_s1[o], accI);
        atomAddLL(&g_s1q[o], accI2);
    }
}

// ---------------- k_bn1: reduce partials, fold BN1 ----------------
__global__ void k_bn1(const float* __restrict__ g, const float* __restrict__ bet) {
    __shared__ long long r1[256], r2[256];
    int t = threadIdx.x;
    long long s = 0, s2 = 0;
    for (int i = t; i < BOXB; i += 256) { s += g_partT[i]; s2 += g_partT2[i]; }
    r1[t] = s; r2[t] = s2; __syncthreads();
    for (int st = 128; st > 0; st >>= 1) {
        if (t < st) { r1[t] += r1[t + st]; r2[t] += r2[t + st]; }
        __syncthreads();
    }
    double sI = (double)r1[0], sI2 = (double)r2[0];
    int o = t;
    if (g_cnt3[o] > 0) { sI = (double)g_s1[o]; sI2 = (double)g_s1q[o]; }
    double mu = sI / (double)NPOS;
    double var = sI2 / (double)NPOS - mu * mu;
    double sc = (double)g_scale1[o];
    double a = (double)g[o] * sc / sqrt(sc * sc * var + EPSV);
    g_a1[o] = (float)a;
    g_c1[o] = (float)((double)bet[o] - a * mu);
}

// ---------------- k_mid FAST: u from x; fp16 u; act2 bits (stored only if bad2); P2 + stats ----------------
__global__ __launch_bounds__(256, 6) void k_mid_f(const float* __restrict__ x,
                                                  const float* __restrict__ b1_2,
                                                  const float* __restrict__ p1a,
                                                  const float* __restrict__ b1_3,
                                                  const float* __restrict__ b2_1) {
    if (g_bad3 != 0) return;
    __shared__ float sa1[256], sK1[256], spa[256], snK3[256];
    __shared__ unsigned sw[8][132];
    __shared__ int rw1[8], rw2[8];
    int tx = threadIdx.x, ty = threadIdx.y, t = ty * 32 + tx;
    sa1[t] = g_a1[t]; sK1[t] = g_c1[t] + b1_2[t];
    spa[t] = p1a[t];  snK3[t] = -(b1_3[t] + b2_1[t]);
    __syncthreads();
    int b = blockIdx.x;
    int p0 = b * PB + tx * 4;
    int n = p0 / SS, s = p0 % SS;
    const float* xp = x + (size_t)n * CS + s;
    __half* up = g_u + (size_t)n * CS + s;
    short4 T4 = *(const short4*)&g_T[p0];
    float Tf0 = T4.x, Tf1 = T4.y, Tf2 = T4.z, Tf3 = T4.w;
    unsigned w0 = 0, w1 = 0, w2 = 0, w3v = 0;
    #pragma unroll
    for (int it = 0; it < 32; it++) {
        int c = ty * 32 + it;
        float4 v = __ldcs((const float4*)(xp + (size_t)c * SS));
        float a = sa1[c], K = sK1[c], pa = spa[c], nK3 = snK3[c];
        float u0 = v.x + fmaf(a, Tf0, K);
        float u1 = v.y + fmaf(a, Tf1, K);
        float u2 = v.z + fmaf(a, Tf2, K);
        float u3 = v.w + fmaf(a, Tf3, K);
        u0 *= (u0 >= 0.f) ? 1.f : pa;
        u1 *= (u1 >= 0.f) ? 1.f : pa;
        u2 *= (u2 >= 0.f) ? 1.f : pa;
        u3 *= (u3 >= 0.f) ? 1.f : pa;
        __half2 h01 = __floats2half2_rn(u0, u1);
        __half2 h23 = __floats2half2_rn(u2, u3);
        uint2 pk;
        pk.x = *reinterpret_cast<unsigned*>(&h01);
        pk.y = *reinterpret_cast<unsigned*>(&h23);
        *reinterpret_cast<uint2*>(up + (size_t)c * SS) = pk;
        w0 |= (unsigned)(u0 >= nK3) << it;
        w1 |= (unsigned)(u1 >= nK3) << it;
        w2 |= (unsigned)(u2 >= nK3) << it;
        w3v |= (unsigned)(u3 >= nK3) << it;
    }
    sw[ty][tx * 4 + 0] = w0; sw[ty][tx * 4 + 1] = w1;
    sw[ty][tx * 4 + 2] = w2; sw[ty][tx * 4 + 3] = w3v;
    __syncthreads();
    if (g_bad2 != 0) {
        #pragma unroll
        for (int i = t; i < 1024; i += 256)
            g_xb2[(size_t)b * 1024 + i] = sw[i & 7][i >> 3];
    }
    int v1 = 0, v2 = 0;
    if (t < 128) {
        int P = 0;
        #pragma unroll
        for (int k = 0; k < 8; k++) P += 2 * __popc(sw[k][t]) - 32;
        g_P2[b * PB + t] = (short)P;
        v1 = P; v2 = P * P;
    }
    #pragma unroll
    for (int m = 16; m > 0; m >>= 1) {
        v1 += __shfl_xor_sync(0xffffffffu, v1, m);
        v2 += __shfl_xor_sync(0xffffffffu, v2, m);
    }
    if ((t & 31) == 0) { rw1[t >> 5] = v1; rw2[t >> 5] = v2; }
    __syncthreads();
    if (t == 0) {
        long long s1 = 0, s2 = 0;
        #pragma unroll
        for (int k = 0; k < 8; k++) { s1 += rw1[k]; s2 += rw2[k]; }
        g_partP2[b] = s1; g_partP2q[b] = s2;
    }
}

// ---------------- k_mid GENERAL (uniform guard; exact; runs only if g_bad3) ----------------
__global__ __launch_bounds__(256) void k_mid_g(const float* __restrict__ x,
                                               const float* __restrict__ b1_2,
                                               const float* __restrict__ p1a,
                                               const float* __restrict__ b1_3,
                                               const float* __restrict__ b2_1) {
    if (g_bad3 == 0) return;
    __shared__ float sa1[256], sK1[256], spa[256], sK3[256];
    __shared__ int   f1[256];
    __shared__ unsigned sw[8][132];
    __shared__ int rw1[8], rw2[8];
    int tx = threadIdx.x, ty = threadIdx.y, t = ty * 32 + tx;
    f1[t] = g_cnt3[t];
    sa1[t] = g_a1[t]; sK1[t] = g_c1[t] + b1_2[t];
    spa[t] = p1a[t];  sK3[t] = b1_3[t] + b2_1[t];
    __syncthreads();
    int b = blockIdx.x;
    int p0 = b * PB + tx * 4;
    int n = p0 / SS, s = p0 % SS;
    const float* xp = x + (size_t)n * CS + s;
    const short* yb = g_y1 + (size_t)n * CC * SS + s;
    short4 T4 = *(const short4*)&g_T[p0];
    float Tf0 = T4.x, Tf1 = T4.y, Tf2 = T4.z, Tf3 = T4.w;
    unsigned w0 = 0, w1 = 0, w2 = 0, w3v = 0;
    #pragma unroll
    for (int it = 0; it < 32; it++) {
        int c = ty * 32 + it;
        float4 v = *(const float4*)(xp + (size_t)c * SS);
        float a = sa1[c], K = sK1[c], pa = spa[c], K3 = sK3[c];
        float I0 = Tf0, I1 = Tf1, I2 = Tf2, I3 = Tf3;
        if (f1[c]) {
            short4 y = *(const short4*)(yb + (size_t)c * SS);
            I0 = y.x; I1 = y.y; I2 = y.z; I3 = y.w;
        }
        float u0 = v.x + fmaf(a, I0, K); u0 = fmaxf(u0, 0.f) + pa * fminf(u0, 0.f);
        float u1 = v.y + fmaf(a, I1, K); u1 = fmaxf(u1, 0.f) + pa * fminf(u1, 0.f);
        float u2 = v.z + fmaf(a, I2, K); u2 = fmaxf(u2, 0.f) + pa * fminf(u2, 0.f);
        float u3 = v.w + fmaf(a, I3, K); u3 = fmaxf(u3, 0.f) + pa * fminf(u3, 0.f);
        w0 |= (unsigned)(u0 + K3 >= 0.f) << it;
        w1 |= (unsigned)(u1 + K3 >= 0.f) << it;
        w2 |= (unsigned)(u2 + K3 >= 0.f) << it;
        w3v |= (unsigned)(u3 + K3 >= 0.f) << it;
    }
    sw[ty][tx * 4 + 0] = w0; sw[ty][tx * 4 + 1] = w1;
    sw[ty][tx * 4 + 2] = w2; sw[ty][tx * 4 + 3] = w3v;
    __syncthreads();
    #pragma unroll
    for (int i = t; i < 1024; i += 256)
        g_xb2[(size_t)b * 1024 + i] = sw[i & 7][i >> 3];
    int v1 = 0, v2 = 0;
    if (t < 128) {
        int P = 0;
        #pragma unroll
        for (int k = 0; k < 8; k++) P += 2 * __popc(sw[k][t]) - 32;
        g_P2[b * PB + t] = (short)P;
        v1 = P; v2 = P * P;
    }
    #pragma unroll
    for (int m = 16; m > 0; m >>= 1) {
        v1 += __shfl_xor_sync(0xffffffffu, v1, m);
        v2 += __shfl_xor_sync(0xffffffffu, v2, m);
    }
    if ((t & 31) == 0) { rw1[t >> 5] = v1; rw2[t >> 5] = v2; }
    __syncthreads();
    if (t == 0) {
        long long s1 = 0, s2 = 0;
        #pragma unroll
        for (int k = 0; k < 8; k++) { s1 += rw1[k]; s2 += rw2[k]; }
        g_partP2[b] = s1; g_partP2q[b] = s2;
    }
}

// ---------------- k_conv2_slow (uniform guard) ----------------
__global__ __launch_bounds__(256) void k_conv2_slow() {
    if (g_bad2 == 0) return;
    int o = threadIdx.x;
    int cnt = g_cnt1[o];
    if (cnt == 0) return;
    int b = blockIdx.x, n = b / HH, h = b % HH;
    const unsigned* ent = &g_ent1[o * 256];
    long long accI = 0, accI2 = 0;
    for (int w = 0; w < WW; w++) {
        int p = n * SS + h * WW + w;
        int I = g_P2[p];
        for (int e = 0; e < cnt; e++) {
            unsigned en = ent[e];
            int neg = en & 1, i = en >> 1;
            unsigned word = g_xb2[p * 8 + (i >> 5)];
            int sx = ((word >> (i & 31)) & 1) ? 1 : -1;
            I += (neg ? -2 : -1) * sx;
        }
        g_y2[(size_t)(n * CC + o) * SS + h * WW + w] = (short)I;
        accI += I; accI2 += (long long)I * I;
    }
    atomAddLL(&g_s2[o], accI);
    atomAddLL(&g_s2q[o], accI2);
}

// ---------------- k_bn2 ----------------
__global__ void k_bn2(const float* __restrict__ g, const float* __restrict__ bet) {
    __shared__ long long r1[256], r2[256];
    int t = threadIdx.x;
    long long s = 0, s2 = 0;
    for (int i = t; i < NBLK; i += 256) { s += g_partP2[i]; s2 += g_partP2q[i]; }
    r1[t] = s; r2[t] = s2; __syncthreads();
    for (int st = 128; st > 0; st >>= 1) {
        if (t < st) { r1[t] += r1[t + st]; r2[t] += r2[t + st]; }
        __syncthreads();
    }
    double sI = (double)r1[0], sI2 = (double)r2[0];
    int o = t;
    if (g_cnt1[o] > 0) { sI = (double)g_s2[o]; sI2 = (double)g_s2q[o]; }
    double mu = sI / (double)NPOS;
    double var = sI2 / (double)NPOS - mu * mu;
    double sc = (double)g_scale2[o];
    double a = (double)g[o] * sc / sqrt(sc * sc * var + EPSV);
    g_a2[o] = (float)a;
    g_c2[o] = (float)((double)bet[o] - a * mu);
}

// ---------------- k_final FAST: out = prelu2(u + a2*P2 + K2) + b23, u from fp16 ----------------
__global__ __launch_bounds__(256, 6) void k_final_f(const float* __restrict__ b1_3,
                                                    const float* __restrict__ b2_2,
                                                    const float* __restrict__ p2a,
                                                    const float* __restrict__ b2_3,
                                                    float* __restrict__ out) {
    if ((g_bad3 | g_bad2) != 0) return;
    __shared__ float sa2[256], sK2[256], spa2[256], sb23[256];
    int tx = threadIdx.x, ty = threadIdx.y, t = ty * 32 + tx;
    sa2[t] = g_a2[t]; sK2[t] = b1_3[t] + g_c2[t] + b2_2[t];
    spa2[t] = p2a[t]; sb23[t] = b2_3[t];
    __syncthreads();
    int b = blockIdx.x;
    int p0 = b * PB + tx * 4;
    int n = p0 / SS, s = p0 % SS;
    const __half* up = g_u + (size_t)n * CS + s;
    float* op = out + (size_t)n * CS + s;
    short4 P4 = *(const short4*)&g_P2[p0];
    float Pf0 = P4.x, Pf1 = P4.y, Pf2 = P4.z, Pf3 = P4.w;
    #pragma unroll
    for (int it = 0; it < 32; it++) {
        int c = ty * 32 + it;
        uint2 pk = __ldcs((const uint2*)(up + (size_t)c * SS));
        __half2 h01 = *reinterpret_cast<__half2*>(&pk.x);
        __half2 h23 = *reinterpret_cast<__half2*>(&pk.y);
        float2 u01 = __half22float2(h01);
        float2 u23 = __half22float2(h23);
        float a2 = sa2[c], K2 = sK2[c], pa2 = spa2[c], b23 = sb23[c];
        float t0 = u01.x + fmaf(a2, Pf0, K2);
        float t1 = u01.y + fmaf(a2, Pf1, K2);
        float t2 = u23.x + fmaf(a2, Pf2, K2);
        float t3 = u23.y + fmaf(a2, Pf3, K2);
        t0 *= (t0 >= 0.f) ? 1.f : pa2;
        t1 *= (t1 >= 0.f) ? 1.f : pa2;
        t2 *= (t2 >= 0.f) ? 1.f : pa2;
        t3 *= (t3 >= 0.f) ? 1.f : pa2;
        float4 o4;
        o4.x = t0 + b23;
        o4.y = t1 + b23;
        o4.z = t2 + b23;
        o4.w = t3 + b23;
        __stcs((float4*)(op + (size_t)c * SS), o4);
    }
}

// ---------------- k_final GENERAL (uniform guard; exact from x) ----------------
__global__ __launch_bounds__(256) void k_final_g(const float* __restrict__ x,
                                                 const float* __restrict__ b1_2,
                                                 const float* __restrict__ p1a,
                                                 const float* __restrict__ b1_3,
                                                 const float* __restrict__ b2_2,
                                                 const float* __restrict__ p2a,
                                                 const float* __restrict__ b2_3,
                                                 float* __restrict__ out) {
    if ((g_bad3 | g_bad2) == 0) return;
    __shared__ float sa1[256], sK1[256], spa1[256];
    __shared__ float sa2[256], sK2[256], spa2[256], sb23[256];
    __shared__ int f1[256], f2[256];
    int tx = threadIdx.x, ty = threadIdx.y, t = ty * 32 + tx;
    f1[t] = g_cnt3[t]; f2[t] = g_cnt1[t];
    sa1[t] = g_a1[t]; sK1[t] = g_c1[t] + b1_2[t]; spa1[t] = p1a[t];
    sa2[t] = g_a2[t]; sK2[t] = b1_3[t] + g_c2[t] + b2_2[t];
    spa2[t] = p2a[t]; sb23[t] = b2_3[t];
    __syncthreads();
    int b = blockIdx.x;
    int p0 = b * PB + tx * 4;
    int n = p0 / SS, s = p0 % SS;
    const float* xp = x + (size_t)n * CS + s;
    const short* y1b = g_y1 + (size_t)n * CC * SS + s;
    const short* y2b = g_y2 + (size_t)n * CC * SS + s;
    float* op = out + (size_t)n * CS + s;
    short4 T4 = *(const short4*)&g_T[p0];
    short4 P4 = *(const short4*)&g_P2[p0];
    float Tf0 = T4.x, Tf1 = T4.y, Tf2 = T4.z, Tf3 = T4.w;
    float Pf0 = P4.x, Pf1 = P4.y, Pf2 = P4.z, Pf3 = P4.w;
    #pragma unroll
    for (int it = 0; it < 32; it++) {
        int c = ty * 32 + it;
        float4 v = *(const float4*)(xp + (size_t)c * SS);
        float a1 = sa1[c], K1 = sK1[c], pa1 = spa1[c];
        float a2 = sa2[c], K2 = sK2[c], pa2 = spa2[c], b23 = sb23[c];
        float I10 = Tf0, I11 = Tf1, I12 = Tf2, I13 = Tf3;
        if (f1[c]) {
            short4 y = *(const short4*)(y1b + (size_t)c * SS);
            I10 = y.x; I11 = y.y; I12 = y.z; I13 = y.w;
        }
        float I20 = Pf0, I21 = Pf1, I22 = Pf2, I23 = Pf3;
        if (f2[c]) {
            short4 y = *(const short4*)(y2b + (size_t)c * SS);
            I20 = y.x; I21 = y.y; I22 = y.z; I23 = y.w;
        }
        float u0 = v.x + fmaf(a1, I10, K1); u0 = fmaxf(u0, 0.f) + pa1 * fminf(u0, 0.f);
        float u1 = v.y + fmaf(a1, I11, K1); u1 = fmaxf(u1, 0.f) + pa1 * fminf(u1, 0.f);
        float u2 = v.z + fmaf(a1, I12, K1); u2 = fmaxf(u2, 0.f) + pa1 * fminf(u2, 0.f);
        float u3 = v.w + fmaf(a1, I13, K1); u3 = fmaxf(u3, 0.f) + pa1 * fminf(u3, 0.f);
        float t0 = u0 + fmaf(a2, I20, K2);
        float t1 = u1 + fmaf(a2, I21, K2);
        float t2 = u2 + fmaf(a2, I22, K2);
        float t3 = u3 + fmaf(a2, I23, K2);
        float4 o4;
        o4.x = fmaxf(t0, 0.f) + pa2 * fminf(t0, 0.f) + b23;
        o4.y = fmaxf(t1, 0.f) + pa2 * fminf(t1, 0.f) + b23;
        o4.z = fmaxf(t2, 0.f) + pa2 * fminf(t2, 0.f) + b23;
        o4.w = fmaxf(t3, 0.f) + pa2 * fminf(t3, 0.f) + b23;
        *(float4*)(op + (size_t)c * SS) = o4;
    }
}

// ---------------- launch ----------------
extern "C" void kernel_launch(void* const* d_in, const int* in_sizes, int n_in,
                              void* d_out, int out_size) {
    const float* x     = (const float*)d_in[0];
    const float* b1_1  = (const float*)d_in[1];
    const float* w3x3  = (const float*)d_in[2];
    const float* bn1_g = (const float*)d_in[3];
    const float* bn1_b = (const float*)d_in[4];
    const float* b1_2  = (const float*)d_in[5];
    const float* p1a   = (const float*)d_in[6];
    const float* b1_3  = (const float*)d_in[7];
    const float* b2_1  = (const float*)d_in[8];
    const float* wres  = (const float*)d_in[9];
    const float* bn2_g = (const float*)d_in[10];
    const float* bn2_b = (const float*)d_in[11];
    const float* b2_2  = (const float*)d_in[12];
    const float* p2a   = (const float*)d_in[13];
    const float* b2_3  = (const float*)d_in[14];
    float* out = (float*)d_out;

    dim3 blk(32, 8);
    k_wprep<<<2 * CC, 256>>>(w3x3, wres);
    kA<<<NBLK, blk>>>(x, b1_1);
    k_boxconv<<<BOXB + NN * HH, 256>>>();
    k_bn1<<<1, 256>>>(bn1_g, bn1_b);
    k_mid_f<<<NBLK, blk>>>(x, b1_2, p1a, b1_3, b2_1);
    k_mid_g<<<NBLK, blk>>>(x, b1_2, p1a, b1_3, b2_1);
    k_conv2_slow<<<NN * HH, 256>>>();
    k_bn2<<<1, 256>>>(bn2_g, bn2_b);
    k_final_f<<<NBLK, blk>>>(b1_3, b2_2, p2a, b2_3, out);
    k_final_g<<<NBLK, blk>>>(x, b1_2, p1a, b1_3, b2_2, p2a, b2_3, out);
}

// round 17
// speedup vs baseline: 1.3669x; 1.3669x over previous
#include <cuda_runtime.h>
#include <cuda_fp16.h>
#include <cstdint>

#define NN   32
#define CC   256
#define HH   56
#define WW   56
#define SS   3136
#define NPOS 100352
#define CS   802816
#define TOT  25690112
#define EPSV 1e-5
#define PB   128
#define NBLK (NPOS/PB)      // 784
#define BOXB (NPOS/256)     // 392

// ---------------- scratch ----------------
__device__ __align__(16) unsigned g_xb [NPOS * 8];
__device__ __align__(16) unsigned g_xb2[NPOS * 8];
__device__ __align__(16) short    g_P  [NPOS];
__device__ __align__(16) short    g_T  [NPOS];
__device__ __align__(16) short    g_P2 [NPOS];
__device__ __align__(16) short    g_y1 [TOT];
__device__ __align__(16) short    g_y2 [TOT];
__device__ __align__(16) __half   g_u  [TOT];     // fast path: fp16 mid value u
__device__ float     g_scale1[CC], g_scale2[CC];
__device__ unsigned  g_ent3[CC * 2304];
__device__ int       g_cnt3[CC];
__device__ unsigned  g_ent1[CC * 256];
__device__ int       g_cnt1[CC];
// Monotone guard flags: statically 0; set (never cleared) by kA's weight-prep
// blocks when any weight <= 0. Weights are constant within a run, so the value
// is deterministic across replays. Consumers of the flags run in LATER
// launches only (mid/conv2/bn/final); kA's own sign blocks do not read them.
__device__ int       g_bad3 = 0, g_bad2 = 0;
__device__ long long g_partT[BOXB], g_partT2[BOXB];
__device__ long long g_partP2[NBLK], g_partP2q[NBLK];
__device__ long long g_s1[CC], g_s1q[CC], g_s2[CC], g_s2q[CC];
__device__ float     g_a1[CC], g_c1[CC], g_a2[CC], g_c2[CC];

__device__ __forceinline__ void atomAddLL(long long* p, long long v) {
    atomicAdd((unsigned long long*)p, (unsigned long long)v);
}

// BN fold: a = gamma*sc / sqrt(sc^2*var + eps), via float rsqrt + 1 Newton step.
__device__ __forceinline__ void bn_fold(double sI, double sI2, float sc, float gam,
                                        float bet, float& a_out, float& c_out) {
    double mu  = sI / (double)NPOS;
    double var = sI2 / (double)NPOS - mu * mu;
    float d = (float)((double)sc * (double)sc * var + (double)EPSV);
    float r = rsqrtf(d);
    r = r * (1.5f - 0.5f * d * r * r);     // Newton: ~1 ulp fp32
    float a = gam * sc * r;
    a_out = a;
    c_out = (float)((double)bet - (double)a * mu);
}

// ---------------- kA: weight-prep blocks (grid prefix) + sign(x+b1_1) bits + P ----------------
__global__ __launch_bounds__(256) void kA(const float* __restrict__ x,
                                          const float* __restrict__ b1_1,
                                          const float* __restrict__ w3,
                                          const float* __restrict__ wr) {
    __shared__ float    sb[256];
    __shared__ unsigned sw[8][132];
    __shared__ float    red[256];
    int b = blockIdx.x;
    int tx = threadIdx.x, ty = threadIdx.y, t = ty * 32 + tx;
    if (b < 2 * CC) {
        if (b < CC) {
            int o = b;
            if (t == 0) { g_cnt3[o] = 0; g_s1[o] = 0; g_s1q[o] = 0; }
            __syncthreads();
            float sum = 0.f;
            for (int j = t; j < 2304; j += 256) {
                float v = w3[o * 2304 + j];
                sum += fabsf(v);
                if (v <= 0.f) {
                    int slot = atomicAdd(&g_cnt3[o], 1);
                    g_ent3[o * 2304 + slot] =
                        (unsigned)(((j / 9) << 5) | ((j % 9) << 1) | (v < 0.f ? 1 : 0));
                }
            }
            red[t] = sum; __syncthreads();
            for (int st = 128; st > 0; st >>= 1) { if (t < st) red[t] += red[t + st]; __syncthreads(); }
            if (t == 0) {
                g_scale1[o] = red[0] / 2304.f;
                if (g_cnt3[o] > 0) atomicExch(&g_bad3, 1);
            }
        } else {
            int o = b - CC;
            if (t == 0) { g_cnt1[o] = 0; g_s2[o] = 0; g_s2q[o] = 0; }
            __syncthreads();
            float v = wr[o * 256 + t];
            if (v <= 0.f) {
                int slot = atomicAdd(&g_cnt1[o], 1);
                g_ent1[o * 256 + slot] = (unsigned)((t << 1) | (v < 0.f ? 1 : 0));
            }
            red[t] = fabsf(v); __syncthreads();
            for (int st = 128; st > 0; st >>= 1) { if (t < st) red[t] += red[t + st]; __syncthreads(); }
            if (t == 0) {
                g_scale2[o] = red[0] / 256.f;
                if (g_cnt1[o] > 0) atomicExch(&g_bad2, 1);
            }
        }
    } else {
        int bs = b - 2 * CC;
        sb[t] = b1_1[t];
        __syncthreads();
        int p0 = bs * PB + tx * 4;
        int n = p0 / SS, s = p0 % SS;
        const float* xp = x + (size_t)n * CS + s;
        unsigned w0 = 0, w1 = 0, w2 = 0, w3v = 0;
        #pragma unroll
        for (int it = 0; it < 32; it++) {
            int c = ty * 32 + it;
            float4 v = *(const float4*)(xp + (size_t)c * SS);
            float nb = -sb[c];
            w0 |= (unsigned)(v.x >= nb) << it;
            w1 |= (unsigned)(v.y >= nb) << it;
            w2 |= (unsigned)(v.z >= nb) << it;
            w3v |= (unsigned)(v.w >= nb) << it;
        }
        sw[ty][tx * 4 + 0] = w0; sw[ty][tx * 4 + 1] = w1;
        sw[ty][tx * 4 + 2] = w2; sw[ty][tx * 4 + 3] = w3v;
        __syncthreads();
        #pragma unroll
        for (int i = t; i < 1024; i += 256)
            g_xb[(size_t)bs * 1024 + i] = sw[i & 7][i >> 3];
        if (t < 128) {
            int P = 0;
            #pragma unroll
            for (int k = 0; k < 8; k++) P += 2 * __popc(sw[k][t]) - 32;
            g_P[bs * PB + t] = (short)P;
        }
    }
}

// ---------------- k_boxconv: T = box3x3(P) + partial stats (+ fused exact conv1) ----------------
__global__ __launch_bounds__(256) void k_boxconv() {
    int b = blockIdx.x, t = threadIdx.x;
    if (b < BOXB) {
        __shared__ int rw1[8], rw2[8];
        int p = b * 256 + t;
        int n = p / SS, s = p % SS;
        int h = s / WW, w = s % WW;
        int T = 0;
        #pragma unroll
        for (int dh = -1; dh <= 1; dh++) {
            int hh = h + dh; if (hh < 0 || hh >= HH) continue;
            #pragma unroll
            for (int dw = -1; dw <= 1; dw++) {
                int ww = w + dw; if (ww < 0 || ww >= WW) continue;
                T += g_P[n * SS + hh * WW + ww];
            }
        }
        g_T[p] = (short)T;
        int v1 = T, v2 = T * T;
        #pragma unroll
        for (int m = 16; m > 0; m >>= 1) {
            v1 += __shfl_xor_sync(0xffffffffu, v1, m);
            v2 += __shfl_xor_sync(0xffffffffu, v2, m);
        }
        if ((t & 31) == 0) { rw1[t >> 5] = v1; rw2[t >> 5] = v2; }
        __syncthreads();
        if (t == 0) {
            long long s1 = 0, s2 = 0;
            #pragma unroll
            for (int k = 0; k < 8; k++) { s1 += rw1[k]; s2 += rw2[k]; }
            g_partT[b] = s1; g_partT2[b] = s2;
        }
    } else {
        if (g_bad3 == 0) return;
        int o = t;
        int cnt = g_cnt3[o];
        if (cnt == 0) return;
        int bb = b - BOXB;
        int n = bb / HH, h = bb % HH;
        const unsigned* ent = &g_ent3[o * 2304];
        long long accI = 0, accI2 = 0;
        for (int w = 0; w < WW; w++) {
            int T = 0;
            for (int dh = -1; dh <= 1; dh++) {
                int hh = h + dh; if (hh < 0 || hh >= HH) continue;
                for (int dw = -1; dw <= 1; dw++) {
                    int ww = w + dw; if (ww < 0 || ww >= WW) continue;
                    T += g_P[n * SS + hh * WW + ww];
                }
            }
            int I = T;
            for (int e = 0; e < cnt; e++) {
                unsigned en = ent[e];
                int neg = en & 1, tap = (en >> 1) & 15, i = en >> 5;
                int hh = h + tap / 3 - 1, ww = w + tap % 3 - 1;
                if (hh >= 0 && hh < HH && ww >= 0 && ww < WW) {
                    unsigned word = g_xb[(n * SS + hh * WW + ww) * 8 + (i >> 5)];
                    int sx = ((word >> (i & 31)) & 1) ? 1 : -1;
                    I += (neg ? -2 : -1) * sx;
                }
            }
            g_y1[(size_t)(n * CC + o) * SS + h * WW + w] = (short)I;
            accI += I; accI2 += (long long)I * I;
        }
        atomAddLL(&g_s1[o], accI);
        atomAddLL(&g_s1q[o], accI2);
    }
}

// ---------------- k_bn1: reduce partials, fold BN1 ----------------
__global__ void k_bn1(const float* __restrict__ g, const float* __restrict__ bet) {
    __shared__ long long r1[256], r2[256];
    int t = threadIdx.x;
    long long s = 0, s2 = 0;
    for (int i = t; i < BOXB; i += 256) { s += g_partT[i]; s2 += g_partT2[i]; }
    r1[t] = s; r2[t] = s2; __syncthreads();
    for (int st = 128; st > 0; st >>= 1) {
        if (t < st) { r1[t] += r1[t + st]; r2[t] += r2[t + st]; }
        __syncthreads();
    }
    double sI = (double)r1[0], sI2 = (double)r2[0];
    int o = t;
    if (g_cnt3[o] > 0) { sI = (double)g_s1[o]; sI2 = (double)g_s1q[o]; }
    bn_fold(sI, sI2, g_scale1[o], g[o], bet[o], g_a1[o], g_c1[o]);
}

// ---------------- k_mid FAST: u from x; fp16 u; act2 bits (stored only if bad2); P2 + stats ----------------
__global__ __launch_bounds__(256, 6) void k_mid_f(const float* __restrict__ x,
                                                  const float* __restrict__ b1_2,
                                                  const float* __restrict__ p1a,
                                                  const float* __restrict__ b1_3,
                                                  const float* __restrict__ b2_1) {
    if (g_bad3 != 0) return;
    __shared__ float sa1[256], sK1[256], spa[256], snK3[256];
    __shared__ unsigned sw[8][132];
    __shared__ int rw1[8], rw2[8];
    int tx = threadIdx.x, ty = threadIdx.y, t = ty * 32 + tx;
    sa1[t] = g_a1[t]; sK1[t] = g_c1[t] + b1_2[t];
    spa[t] = p1a[t];  snK3[t] = -(b1_3[t] + b2_1[t]);
    __syncthreads();
    int b = blockIdx.x;
    int p0 = b * PB + tx * 4;
    int n = p0 / SS, s = p0 % SS;
    const float* xp = x + (size_t)n * CS + s;
    __half* up = g_u + (size_t)n * CS + s;
    short4 T4 = *(const short4*)&g_T[p0];
    float Tf0 = T4.x, Tf1 = T4.y, Tf2 = T4.z, Tf3 = T4.w;
    unsigned w0 = 0, w1 = 0, w2 = 0, w3v = 0;
    #pragma unroll
    for (int it = 0; it < 32; it++) {
        int c = ty * 32 + it;
        float4 v = __ldcs((const float4*)(xp + (size_t)c * SS));
        float a = sa1[c], K = sK1[c], pa = spa[c], nK3 = snK3[c];
        float u0 = v.x + fmaf(a, Tf0, K);
        float u1 = v.y + fmaf(a, Tf1, K);
        float u2 = v.z + fmaf(a, Tf2, K);
        float u3 = v.w + fmaf(a, Tf3, K);
        u0 *= (u0 >= 0.f) ? 1.f : pa;
        u1 *= (u1 >= 0.f) ? 1.f : pa;
        u2 *= (u2 >= 0.f) ? 1.f : pa;
        u3 *= (u3 >= 0.f) ? 1.f : pa;
        __half2 h01 = __floats2half2_rn(u0, u1);
        __half2 h23 = __floats2half2_rn(u2, u3);
        uint2 pk;
        pk.x = *reinterpret_cast<unsigned*>(&h01);
        pk.y = *reinterpret_cast<unsigned*>(&h23);
        *reinterpret_cast<uint2*>(up + (size_t)c * SS) = pk;
        w0 |= (unsigned)(u0 >= nK3) << it;
        w1 |= (unsigned)(u1 >= nK3) << it;
        w2 |= (unsigned)(u2 >= nK3) << it;
        w3v |= (unsigned)(u3 >= nK3) << it;
    }
    sw[ty][tx * 4 + 0] = w0; sw[ty][tx * 4 + 1] = w1;
    sw[ty][tx * 4 + 2] = w2; sw[ty][tx * 4 + 3] = w3v;
    __syncthreads();
    if (g_bad2 != 0) {
        #pragma unroll
        for (int i = t; i < 1024; i += 256)
            g_xb2[(size_t)b * 1024 + i] = sw[i & 7][i >> 3];
    }
    int v1 = 0, v2 = 0;
    if (t < 128) {
        int P = 0;
        #pragma unroll
        for (int k = 0; k < 8; k++) P += 2 * __popc(sw[k][t]) - 32;
        g_P2[b * PB + t] = (short)P;
        v1 = P; v2 = P * P;
    }
    #pragma unroll
    for (int m = 16; m > 0; m >>= 1) {
        v1 += __shfl_xor_sync(0xffffffffu, v1, m);
        v2 += __shfl_xor_sync(0xffffffffu, v2, m);
    }
    if ((t & 31) == 0) { rw1[t >> 5] = v1; rw2[t >> 5] = v2; }
    __syncthreads();
    if (t == 0) {
        long long s1 = 0, s2 = 0;
        #pragma unroll
        for (int k = 0; k < 8; k++) { s1 += rw1[k]; s2 += rw2[k]; }
        g_partP2[b] = s1; g_partP2q[b] = s2;
    }
}

// ---------------- k_mid GENERAL (uniform guard; exact; runs only if g_bad3) ----------------
__global__ __launch_bounds__(256) void k_mid_g(const float* __restrict__ x,
                                               const float* __restrict__ b1_2,
                                               const float* __restrict__ p1a,
                                               const float* __restrict__ b1_3,
                                               const float* __restrict__ b2_1) {
    if (g_bad3 == 0) return;
    __shared__ float sa1[256], sK1[256], spa[256], sK3[256];
    __shared__ int   f1[256];
    __shared__ unsigned sw[8][132];
    __shared__ int rw1[8], rw2[8];
    int tx = threadIdx.x, ty = threadIdx.y, t = ty * 32 + tx;
    f1[t] = g_cnt3[t];
    sa1[t] = g_a1[t]; sK1[t] = g_c1[t] + b1_2[t];
    spa[t] = p1a[t];  sK3[t] = b1_3[t] + b2_1[t];
    __syncthreads();
    int b = blockIdx.x;
    int p0 = b * PB + tx * 4;
    int n = p0 / SS, s = p0 % SS;
    const float* xp = x + (size_t)n * CS + s;
    const short* yb = g_y1 + (size_t)n * CC * SS + s;
    short4 T4 = *(const short4*)&g_T[p0];
    float Tf0 = T4.x, Tf1 = T4.y, Tf2 = T4.z, Tf3 = T4.w;
    unsigned w0 = 0, w1 = 0, w2 = 0, w3v = 0;
    #pragma unroll
    for (int it = 0; it < 32; it++) {
        int c = ty * 32 + it;
        float4 v = *(const float4*)(xp + (size_t)c * SS);
        float a = sa1[c], K = sK1[c], pa = spa[c], K3 = sK3[c];
        float I0 = Tf0, I1 = Tf1, I2 = Tf2, I3 = Tf3;
        if (f1[c]) {
            short4 y = *(const short4*)(yb + (size_t)c * SS);
            I0 = y.x; I1 = y.y; I2 = y.z; I3 = y.w;
        }
        float u0 = v.x + fmaf(a, I0, K); u0 = fmaxf(u0, 0.f) + pa * fminf(u0, 0.f);
        float u1 = v.y + fmaf(a, I1, K); u1 = fmaxf(u1, 0.f) + pa * fminf(u1, 0.f);
        float u2 = v.z + fmaf(a, I2, K); u2 = fmaxf(u2, 0.f) + pa * fminf(u2, 0.f);
        float u3 = v.w + fmaf(a, I3, K); u3 = fmaxf(u3, 0.f) + pa * fminf(u3, 0.f);
        w0 |= (unsigned)(u0 + K3 >= 0.f) << it;
        w1 |= (unsigned)(u1 + K3 >= 0.f) << it;
        w2 |= (unsigned)(u2 + K3 >= 0.f) << it;
        w3v |= (unsigned)(u3 + K3 >= 0.f) << it;
    }
    sw[ty][tx * 4 + 0] = w0; sw[ty][tx * 4 + 1] = w1;
    sw[ty][tx * 4 + 2] = w2; sw[ty][tx * 4 + 3] = w3v;
    __syncthreads();
    #pragma unroll
    for (int i = t; i < 1024; i += 256)
        g_xb2[(size_t)b * 1024 + i] = sw[i & 7][i >> 3];
    int v1 = 0, v2 = 0;
    if (t < 128) {
        int P = 0;
        #pragma unroll
        for (int k = 0; k < 8; k++) P += 2 * __popc(sw[k][t]) - 32;
        g_P2[b * PB + t] = (short)P;
        v1 = P; v2 = P * P;
    }
    #pragma unroll
    for (int m = 16; m > 0; m >>= 1) {
        v1 += __shfl_xor_sync(0xffffffffu, v1, m);
        v2 += __shfl_xor_sync(0xffffffffu, v2, m);
    }
    if ((t & 31) == 0) { rw1[t >> 5] = v1; rw2[t >> 5] = v2; }
    __syncthreads();
    if (t == 0) {
        long long s1 = 0, s2 = 0;
        #pragma unroll
        for (int k = 0; k < 8; k++) { s1 += rw1[k]; s2 += rw2[k]; }
        g_partP2[b] = s1; g_partP2q[b] = s2;
    }
}

// ---------------- k_conv2_slow (uniform guard) ----------------
__global__ __launch_bounds__(256) void k_conv2_slow() {
    if (g_bad2 == 0) return;
    int o = threadIdx.x;
    int cnt = g_cnt1[o];
    if (cnt == 0) return;
    int b = blockIdx.x, n = b / HH, h = b % HH;
    const unsigned* ent = &g_ent1[o * 256];
    long long accI = 0, accI2 = 0;
    for (int w = 0; w < WW; w++) {
        int p = n * SS + h * WW + w;
        int I = g_P2[p];
        for (int e = 0; e < cnt; e++) {
            unsigned en = ent[e];
            int neg = en & 1, i = en >> 1;
            unsigned word = g_xb2[p * 8 + (i >> 5)];
            int sx = ((word >> (i & 31)) & 1) ? 1 : -1;
            I += (neg ? -2 : -1) * sx;
        }
        g_y2[(size_t)(n * CC + o) * SS + h * WW + w] = (short)I;
        accI += I; accI2 += (long long)I * I;
    }
    atomAddLL(&g_s2[o], accI);
    atomAddLL(&g_s2q[o], accI2);
}

// ---------------- k_bn2 ----------------
__global__ void k_bn2(const float* __restrict__ g, const float* __restrict__ bet) {
    __shared__ long long r1[256], r2[256];
    int t = threadIdx.x;
    long long s = 0, s2 = 0;
    for (int i = t; i < NBLK; i += 256) { s += g_partP2[i]; s2 += g_partP2q[i]; }
    r1[t] = s; r2[t] = s2; __syncthreads();
    for (int st = 128; st > 0; st >>= 1) {
        if (t < st) { r1[t] += r1[t + st]; r2[t] += r2[t + st]; }
        __syncthreads();
    }
    double sI = (double)r1[0], sI2 = (double)r2[0];
    int o = t;
    if (g_cnt1[o] > 0) { sI = (double)g_s2[o]; sI2 = (double)g_s2q[o]; }
    bn_fold(sI, sI2, g_scale2[o], g[o], bet[o], g_a2[o], g_c2[o]);
}

// ---------------- k_final FAST: out = prelu2(u + a2*P2 + K2) + b23, u from fp16 ----------------
__global__ __launch_bounds__(256, 6) void k_final_f(const float* __restrict__ b1_3,
                                                    const float* __restrict__ b2_2,
                                                    const float* __restrict__ p2a,
                                                    const float* __restrict__ b2_3,
                                                    float* __restrict__ out) {
    if ((g_bad3 | g_bad2) != 0) return;
    __shared__ float sa2[256], sK2[256], spa2[256], sb23[256];
    int tx = threadIdx.x, ty = threadIdx.y, t = ty * 32 + tx;
    sa2[t] = g_a2[t]; sK2[t] = b1_3[t] + g_c2[t] + b2_2[t];
    spa2[t] = p2a[t]; sb23[t] = b2_3[t];
    __syncthreads();
    int b = blockIdx.x;
    int p0 = b * PB + tx * 4;
    int n = p0 / SS, s = p0 % SS;
    const __half* up = g_u + (size_t)n * CS + s;
    float* op = out + (size_t)n * CS + s;
    short4 P4 = *(const short4*)&g_P2[p0];
    float Pf0 = P4.x, Pf1 = P4.y, Pf2 = P4.z, Pf3 = P4.w;
    #pragma unroll
    for (int it = 0; it < 32; it++) {
        int c = ty * 32 + it;
        uint2 pk = __ldcs((const uint2*)(up + (size_t)c * SS));
        __half2 h01 = *reinterpret_cast<__half2*>(&pk.x);
        __half2 h23 = *reinterpret_cast<__half2*>(&pk.y);
        float2 u01 = __half22float2(h01);
        float2 u23 = __half22float2(h23);
        float a2 = sa2[c], K2 = sK2[c], pa2 = spa2[c], b23 = sb23[c];
        float t0 = u01.x + fmaf(a2, Pf0, K2);
        float t1 = u01.y + fmaf(a2, Pf1, K2);
        float t2 = u23.x + fmaf(a2, Pf2, K2);
        float t3 = u23.y + fmaf(a2, Pf3, K2);
        t0 *= (t0 >= 0.f) ? 1.f : pa2;
        t1 *= (t1 >= 0.f) ? 1.f : pa2;
        t2 *= (t2 >= 0.f) ? 1.f : pa2;
        t3 *= (t3 >= 0.f) ? 1.f : pa2;
        float4 o4;
        o4.x = t0 + b23;
        o4.y = t1 + b23;
        o4.z = t2 + b23;
        o4.w = t3 + b23;
        __stcs((float4*)(op + (size_t)c * SS), o4);
    }
}

// ---------------- k_final GENERAL (uniform guard; exact from x) ----------------
__global__ __launch_bounds__(256) void k_final_g(const float* __restrict__ x,
                                                 const float* __restrict__ b1_2,
                                                 const float* __restrict__ p1a,
                                                 const float* __restrict__ b1_3,
                                                 const float* __restrict__ b2_2,
                                                 const float* __restrict__ p2a,
                                                 const float* __restrict__ b2_3,
                                                 float* __restrict__ out) {
    if ((g_bad3 | g_bad2) == 0) return;
    __shared__ float sa1[256], sK1[256], spa1[256];
    __shared__ float sa2[256], sK2[256], spa2[256], sb23[256];
    __shared__ int f1[256], f2[256];
    int tx = threadIdx.x, ty = threadIdx.y, t = ty * 32 + tx;
    f1[t] = g_cnt3[t]; f2[t] = g_cnt1[t];
    sa1[t] = g_a1[t]; sK1[t] = g_c1[t] + b1_2[t]; spa1[t] = p1a[t];
    sa2[t] = g_a2[t]; sK2[t] = b1_3[t] + g_c2[t] + b2_2[t];
    spa2[t] = p2a[t]; sb23[t] = b2_3[t];
    __syncthreads();
    int b = blockIdx.x;
    int p0 = b * PB + tx * 4;
    int n = p0 / SS, s = p0 % SS;
    const float* xp = x + (size_t)n * CS + s;
    const short* y1b = g_y1 + (size_t)n * CC * SS + s;
    const short* y2b = g_y2 + (size_t)n * CC * SS + s;
    float* op = out + (size_t)n * CS + s;
    short4 T4 = *(const short4*)&g_T[p0];
    short4 P4 = *(const short4*)&g_P2[p0];
    float Tf0 = T4.x, Tf1 = T4.y, Tf2 = T4.z, Tf3 = T4.w;
    float Pf0 = P4.x, Pf1 = P4.y, Pf2 = P4.z, Pf3 = P4.w;
    #pragma unroll
    for (int it = 0; it < 32; it++) {
        int c = ty * 32 + it;
        float4 v = *(const float4*)(xp + (size_t)c * SS);
        float a1 = sa1[c], K1 = sK1[c], pa1 = spa1[c];
        float a2 = sa2[c], K2 = sK2[c], pa2 = spa2[c], b23 = sb23[c];
        float I10 = Tf0, I11 = Tf1, I12 = Tf2, I13 = Tf3;
        if (f1[c]) {
            short4 y = *(const short4*)(y1b + (size_t)c * SS);
            I10 = y.x; I11 = y.y; I12 = y.z; I13 = y.w;
        }
        float I20 = Pf0, I21 = Pf1, I22 = Pf2, I23 = Pf3;
        if (f2[c]) {
            short4 y = *(const short4*)(y2b + (size_t)c * SS);
            I20 = y.x; I21 = y.y; I22 = y.z; I23 = y.w;
        }
        float u0 = v.x + fmaf(a1, I10, K1); u0 = fmaxf(u0, 0.f) + pa1 * fminf(u0, 0.f);
        float u1 = v.y + fmaf(a1, I11, K1); u1 = fmaxf(u1, 0.f) + pa1 * fminf(u1, 0.f);
        float u2 = v.z + fmaf(a1, I12, K1); u2 = fmaxf(u2, 0.f) + pa1 * fminf(u2, 0.f);
        float u3 = v.w + fmaf(a1, I13, K1); u3 = fmaxf(u3, 0.f) + pa1 * fminf(u3, 0.f);
        float t0 = u0 + fmaf(a2, I20, K2);
        float t1 = u1 + fmaf(a2, I21, K2);
        float t2 = u2 + fmaf(a2, I22, K2);
        float t3 = u3 + fmaf(a2, I23, K2);
        float4 o4;
        o4.x = fmaxf(t0, 0.f) + pa2 * fminf(t0, 0.f) + b23;
        o4.y = fmaxf(t1, 0.f) + pa2 * fminf(t1, 0.f) + b23;
        o4.z = fmaxf(t2, 0.f) + pa2 * fminf(t2, 0.f) + b23;
        o4.w = fmaxf(t3, 0.f) + pa2 * fminf(t3, 0.f) + b23;
        *(float4*)(op + (size_t)c * SS) = o4;
    }
}

// ---------------- launch ----------------
extern "C" void kernel_launch(void* const* d_in, const int* in_sizes, int n_in,
                              void* d_out, int out_size) {
    const float* x     = (const float*)d_in[0];
    const float* b1_1  = (const float*)d_in[1];
    const float* w3x3  = (const float*)d_in[2];
    const float* bn1_g = (const float*)d_in[3];
    const float* bn1_b = (const float*)d_in[4];
    const float* b1_2  = (const float*)d_in[5];
    const float* p1a   = (const float*)d_in[6];
    const float* b1_3  = (const float*)d_in[7];
    const float* b2_1  = (const float*)d_in[8];
    const float* wres  = (const float*)d_in[9];
    const float* bn2_g = (const float*)d_in[10];
    const float* bn2_b = (const float*)d_in[11];
    const float* b2_2  = (const float*)d_in[12];
    const float* p2a   = (const float*)d_in[13];
    const float* b2_3  = (const float*)d_in[14];
    float* out = (float*)d_out;

    dim3 blk(32, 8);
    kA<<<NBLK + 2 * CC, blk>>>(x, b1_1, w3x3, wres);
    k_boxconv<<<BOXB + NN * HH, 256>>>();
    k_bn1<<<1, 256>>>(bn1_g, bn1_b);
    k_mid_f<<<NBLK, blk>>>(x, b1_2, p1a, b1_3, b2_1);
    k_mid_g<<<NBLK, blk>>>(x, b1_2, p1a, b1_3, b2_1);
    k_conv2_slow<<<NN * HH, 256>>>();
    k_bn2<<<1, 256>>>(bn2_g, bn2_b);
    k_final_f<<<NBLK, blk>>>(b1_3, b2_2, p2a, b2_3, out);
    k_final_g<<<NBLK, blk>>>(x, b1_2, p1a, b1_3, b2_2, p2a, b2_3, out);
}